// round 12
// baseline (speedup 1.0000x reference)
#include <cuda_runtime.h>

#define NK 5000
#define BB 512
#define TT 100

__device__ __forceinline__ float sigm(float x) {
    return 1.f / (1.f + __expf(-x));
}

// One CTA per batch row, single kernel (no table-build launch).
//
// The BKT recurrence only carries a dependency through index collisions:
//   skill(t) = pred(prev(t)) where prev(t) = last t'<t with pks[t']==pks[t],
//              else sigmoid(logits[pks[t],4])
//   cs(t)    = pred(tc(t))   where tc(t)  = last t'<=t with pks[t']==cks[t],
//              else sigmoid(logits[cks[t],4])
// With 100 draws from 5000 KCs the dependency forest is ~depth 2-3, so the
// "serial" chain is resolved in a handful of fully-parallel rounds.
//
// Warps 0-3: gather + search + depth-ordered rounds + probs + state fixup.
// Warps 4-7 (overlapped): stream init state sigmoid(logits[:,4]) to gmem;
//   the <=99 updated entries are fixed up after a block-wide sync.
__global__ __launch_bounds__(256, 1) void bkt_kernel(
    const int* __restrict__ prev_kc,
    const int* __restrict__ curr_kc,
    const int* __restrict__ prev_corr,
    const float* __restrict__ logits,
    float* __restrict__ out)
{
    __shared__ int   s_pks[TT];
    __shared__ int   s_prev[TT];
    __shared__ float s_pred[TT];
    __shared__ int   s_wmax[4];

    const int b = blockIdx.x;
    const int tid = threadIdx.x;
    float* probOut  = out + b * TT;
    float* stateOut = out + BB * TT + b * NK;

    // Registers that survive into the post-sync fixup:
    int   pk = -1;
    bool  islast = false;
    float myPred = 0.f;
    bool  doFix = false;

    if (tid < 128) {
        const int  t      = tid;
        const bool active = (t < TT);

        // ---- Phase A: gathers, sigmoids, per-thread chain constants ----
        int   ck = 0;
        float Cx = 0.f, Cy = 0.f, Cz = 0.f, Cw = 0.f;
        float Px = 0.f, Py = 0.f, skill0 = 0.f, ckinit = 0.f;
        if (active) {
            ck = curr_kc[b * TT + t];
            if (t >= 1) {
                pk = prev_kc[b * TT + t];
                const int c = prev_corr[b * TT + t];
                const float* rp = logits + pk * 5;
                const float pvx = sigm(rp[0]);
                const float pvy = sigm(rp[1]);
                const float pvz = sigm(rp[2]);
                const float pvw = sigm(rp[3]);
                skill0 = sigm(rp[4]);
                const float p2 = c ? pvz : 1.f - pvz;   // p_out[0]
                const float p3 = c ? pvw : 1.f - pvw;   // p_out[1]
                Cx = p2;  Cy = p3 - p2;  Cz = pvx;
                Cw = (1.f - pvy - pvx) * p3;            // pred = Cz + Cw*sk/den
            }
            const float* cp = logits + ck * 5;
            const float cvz = sigm(cp[2]);
            const float cvw = sigm(cp[3]);
            ckinit = sigm(cp[4]);
            Px = cvz;  Py = cvw - cvz;                  // prob = fma(cs,Py,Px)
            s_pks[t] = pk;                              // s_pks[0] = -1 sentinel
        }
        asm volatile("bar.sync 1, 128;" ::: "memory");

        // ---- Search: prev / tc / islast via broadcast-LDS sweep ----
        int prev = 0, tc = 0;
        islast = true;
        #pragma unroll 4
        for (int u = 1; u < TT; ++u) {
            const int pu = s_pks[u];                    // broadcast, conflict-free
            if (active) {
                if (pu == pk) {
                    if (u < t)      prev = u;           // ascending keeps max
                    else if (u > t) islast = false;
                }
                if (pu == ck && u <= t) tc = u;
            }
        }
        if (active) s_prev[t] = prev;
        asm volatile("bar.sync 1, 128;" ::: "memory");

        // ---- Depth of each node in the dependency forest ----
        int depth = 0;
        if (active && t >= 1)
            for (int c2 = prev; c2 != 0; c2 = s_prev[c2]) depth++;
        int wm = __reduce_max_sync(0xffffffffu, depth);
        if ((tid & 31) == 0) s_wmax[tid >> 5] = wm;
        asm volatile("bar.sync 1, 128;" ::: "memory");
        const int maxd = max(max(s_wmax[0], s_wmax[1]),
                             max(s_wmax[2], s_wmax[3]));

        // ---- Rounds: resolve preds in depth order (1 barrier/round) ----
        for (int r = 0; r <= maxd; ++r) {
            if (active && t >= 1 && depth == r) {
                const float sk  = prev ? s_pred[prev] : skill0;
                const float den = fmaf(Cy, sk, Cx);
                myPred = Cz + __fdividef(Cw * sk, den);
                s_pred[t] = myPred;
            }
            asm volatile("bar.sync 1, 128;" ::: "memory");
        }

        // ---- Probs ----
        if (active) {
            const float cs = tc ? s_pred[tc] : ckinit;
            probOut[t] = fmaf(cs, Py, Px);
        }
        doFix = active && (t >= 1) && islast;
    } else {
        // ---- Overlapped: stream init state directly from logits ----
        for (int k = tid - 128; k < NK; k += 128)
            stateOut[k] = sigm(logits[k * 5 + 4]);
    }
    __syncthreads();

    // ---- Fixup: last occurrence of each pk overwrites with final pred ----
    if (doFix) stateOut[pk] = myPred;
}

extern "C" void kernel_launch(void* const* d_in, const int* in_sizes, int n_in,
                              void* d_out, int out_size) {
    const int*   prev_kc   = (const int*)d_in[0];
    const int*   curr_kc   = (const int*)d_in[1];
    const int*   prev_corr = (const int*)d_in[2];
    const float* logits    = (const float*)d_in[3];
    float*       out       = (float*)d_out;

    bkt_kernel<<<BB, 256>>>(prev_kc, curr_kc, prev_corr, logits, out);
}